// round 13
// baseline (speedup 1.0000x reference)
#include <cuda_runtime.h>

// OTTT step: s, u_new = LIF(sig_tau*u + x@W + b); a_hat_new = sig_tau*a_hat + x
// Inputs (metadata order): W [8192*8192] f32, b [8192], u [8192], a_hat [8192], x [8192]
// Output: flat [s(8192) | u_new(8192) | a_hat_new(8192)] f32
//
// Dynamic-work-stealing split-K GEMV: 512 CTAs, 64 per j-block, pulling 4-row
// chunks from per-jb atomic queues (kills the ~10% CTA straggler spread that
// every static-assignment variant paid as a ~6us tail). Determinism: each
// chunk's partial is quantized to int64 fixed point and accumulated with
// exact commutative integer adds -> bit-identical result for any schedule.

#define IN_DIM  8192
#define OUT_DIM 8192
#define TPB     256
#define JPT     4                          // columns per thread (float4)
#define JPB     (TPB * JPT)                // 1024 columns per block
#define JBLOCKS (OUT_DIM / JPB)            // 8
#define CTAS_PER_JB 64
#define NCTAS   (JBLOCKS * CTAS_PER_JB)    // 512
#define CROWS   4                          // rows per work chunk
#define NCHUNK  (IN_DIM / CROWS)           // 2048 chunks per j-block

// sigmoid(2.0)
#define SIG_TAU 0.8807970779778823f
#define V_TH    1.0f

// fixed-point scale 2^42: per-chunk |partial| small; 2048 chunks of 2^-42
// rounding -> ~5e-10 absolute, invisible at 1e-3 tolerance.
#define FP_SCALE    4398046511104.0        // 2^42
#define FP_INVSCALE (1.0 / 4398046511104.0)

__device__ unsigned long long g_acc[OUT_DIM];  // zero at load; epilogue resets
__device__ unsigned int       g_work[JBLOCKS]; // zero at load; epilogue resets

__global__ void __launch_bounds__(TPB, 4) gemv_dynamic(
    const float* __restrict__ W, const float* __restrict__ x)
{
    const int jb = blockIdx.x & (JBLOCKS - 1);      // 0..7
    const int j0 = jb * JPB + threadIdx.x * JPT;
    const int c4 = j0 >> 2;

    __shared__ float    xs[IN_DIM];                 // 32 KB: full x vector
    __shared__ unsigned s_chunk;

    // stage x once (coalesced float4)
    {
        const float4* __restrict__ xv4 = reinterpret_cast<const float4*>(x);
        float4* __restrict__ xs4 = reinterpret_cast<float4*>(xs);
        #pragma unroll
        for (int i = 0; i < IN_DIM / 4 / TPB; ++i)
            xs4[threadIdx.x + i * TPB] = xv4[threadIdx.x + i * TPB];
    }
    if (threadIdx.x == 0)
        s_chunk = atomicAdd(&g_work[jb], 1u);
    __syncthreads();

    const float4* __restrict__ Wv = reinterpret_cast<const float4*>(W);
    const size_t row_v4 = OUT_DIM / 4;

    long long q0 = 0, q1 = 0, q2 = 0, q3 = 0;       // exact int64 accumulators
    unsigned cur = s_chunk;

    while (cur < NCHUNK) {
        __syncthreads();                            // s_chunk consumed by all
        if (threadIdx.x == 0)
            s_chunk = atomicAdd(&g_work[jb], 1u);   // prefetch next chunk id

        const int r0 = cur * CROWS;
        float ax = 0.f, ay = 0.f, az = 0.f, aw = 0.f;
        #pragma unroll
        for (int k = 0; k < CROWS; ++k) {
            // streaming load: W never reused — evict-first in L2
            float4 w = __ldcs(Wv + (size_t)(r0 + k) * row_v4 + c4);
            float xv = xs[r0 + k];
            ax = fmaf(xv, w.x, ax);
            ay = fmaf(xv, w.y, ay);
            az = fmaf(xv, w.z, az);
            aw = fmaf(xv, w.w, aw);
        }
        // per-chunk quantization: fixed rounding per fixed chunk; int adds
        // commute exactly -> schedule-independent deterministic sum.
        q0 += __double2ll_rn((double)ax * FP_SCALE);
        q1 += __double2ll_rn((double)ay * FP_SCALE);
        q2 += __double2ll_rn((double)az * FP_SCALE);
        q3 += __double2ll_rn((double)aw * FP_SCALE);

        __syncthreads();                            // s_chunk updated
        cur = s_chunk;
    }

    atomicAdd(&g_acc[j0 + 0], (unsigned long long)q0);
    atomicAdd(&g_acc[j0 + 1], (unsigned long long)q1);
    atomicAdd(&g_acc[j0 + 2], (unsigned long long)q2);
    atomicAdd(&g_acc[j0 + 3], (unsigned long long)q3);

    // let the PDL epilogue start launching/prefetching while we drain
    cudaTriggerProgrammaticLaunchCompletion();
}

// Epilogue (PDL secondary): 8192 threads, one output column each.
// Pre-sync: a_hat trace (GEMV-independent). Post-sync: read L2-hot 64KB
// accumulator, convert, LIF; reset accumulator + work queues for replay.
#define EPI_TPB    256
#define EPI_BLOCKS (OUT_DIM / EPI_TPB)     // 32

__global__ void __launch_bounds__(EPI_TPB) lif_epilogue(
    const float* __restrict__ b, const float* __restrict__ u,
    const float* __restrict__ a_hat, const float* __restrict__ x,
    float* __restrict__ out)
{
    const int j = blockIdx.x * EPI_TPB + threadIdx.x;

    // ---- GEMV-independent work before waiting ----
    const float bj = b[j];
    const float uj = u[j];
    out[2 * OUT_DIM + j] = fmaf(SIG_TAU, a_hat[j], x[j]);   // a_hat_new

    // ---- wait for the GEMV grid's memory to be visible ----
    cudaGridDependencySynchronize();

    const long long q = (long long)g_acc[j];
    g_acc[j] = 0ULL;                        // sole reader: reset for replay
    if (j < JBLOCKS) g_work[j] = 0u;        // reset work queues for replay

    const float acc   = (float)((double)q * FP_INVSCALE);
    const float u_pre = fmaf(SIG_TAU, uj, acc + bj);
    const float spike = (u_pre >= V_TH) ? 1.0f : 0.0f;

    out[j]           = spike;
    out[OUT_DIM + j] = u_pre - spike * V_TH;
}

extern "C" void kernel_launch(void* const* d_in, const int* in_sizes, int n_in,
                              void* d_out, int out_size)
{
    const float* W     = (const float*)d_in[0];
    const float* b     = (const float*)d_in[1];
    const float* u     = (const float*)d_in[2];
    const float* a_hat = (const float*)d_in[3];
    const float* x     = (const float*)d_in[4];
    float* out = (float*)d_out;

    gemv_dynamic<<<NCTAS, TPB>>>(W, x);

    // PDL secondary: may launch while gemv_dynamic drains.
    cudaLaunchConfig_t cfg = {};
    cfg.gridDim  = dim3(EPI_BLOCKS, 1, 1);
    cfg.blockDim = dim3(EPI_TPB, 1, 1);
    cfg.dynamicSmemBytes = 0;
    cfg.stream = 0;
    cudaLaunchAttribute attr[1];
    attr[0].id = cudaLaunchAttributeProgrammaticStreamSerialization;
    attr[0].val.programmaticStreamSerializationAllowed = 1;
    cfg.attrs = attr;
    cfg.numAttrs = 1;
    cudaLaunchKernelEx(&cfg, lif_epilogue, b, u, a_hat, x, out);
}

// round 14
// speedup vs baseline: 1.5525x; 1.5525x over previous
#include <cuda_runtime.h>

// OTTT step: s, u_new = LIF(sig_tau*u + x@W + b); a_hat_new = sig_tau*a_hat + x
// Inputs (metadata order): W [8192*8192] f32, b [8192], u [8192], a_hat [8192], x [8192]
// Output: flat [s(8192) | u_new(8192) | a_hat_new(8192)] f32
//
// Work-stealing split-K GEMV: 512 CTAs (64 per j-block) pull 8-row chunks from
// per-jb atomic queues, so fast SMs absorb the slow SMs' work (kills the ~10%
// straggler-spread tail of static assignment). Determinism: per-chunk partials
// are quantized to int64 fixed point; integer adds commute exactly, so the
// result is bit-identical for any schedule. One __syncthreads per chunk via
// double-buffered chunk ids. PDL epilogue converts + LIF + resets state.

#define IN_DIM  8192
#define OUT_DIM 8192
#define TPB     256
#define JPT     4                          // columns per thread (float4)
#define JPB     (TPB * JPT)                // 1024 columns per block
#define JBLOCKS (OUT_DIM / JPB)            // 8
#define CTAS_PER_JB 64
#define NCTAS   (JBLOCKS * CTAS_PER_JB)    // 512
#define CROWS   8                          // rows per work chunk
#define NCHUNK  (IN_DIM / CROWS)           // 1024 chunks per j-block

// sigmoid(2.0)
#define SIG_TAU 0.8807970779778823f
#define V_TH    1.0f

// fixed-point scale 2^42: chunk partials are O(1); 1024 chunks of 2^-42
// rounding -> ~2e-10 absolute error, invisible at the 1e-3 tolerance.
#define FP_SCALE    4398046511104.0        // 2^42
#define FP_INVSCALE (1.0 / 4398046511104.0)

__device__ unsigned long long g_acc[OUT_DIM];  // zero at load; epilogue resets
__device__ unsigned int       g_work[JBLOCKS]; // zero at load; epilogue resets

__global__ void __launch_bounds__(TPB) gemv_steal(
    const float* __restrict__ W, const float* __restrict__ x)
{
    const int jb = blockIdx.x & (JBLOCKS - 1);      // 0..7
    const int j0 = jb * JPB + threadIdx.x * JPT;
    const int c4 = j0 >> 2;

    __shared__ float    xs[IN_DIM];                 // 32 KB: full x vector
    __shared__ unsigned s_buf[2];                   // double-buffered chunk ids

    // stage x once (coalesced float4; L2-served after first CTA touches it)
    {
        const float4* __restrict__ xv4 = reinterpret_cast<const float4*>(x);
        float4* __restrict__ xs4 = reinterpret_cast<float4*>(xs);
        #pragma unroll
        for (int i = 0; i < IN_DIM / 4 / TPB; ++i)
            xs4[threadIdx.x + i * TPB] = xv4[threadIdx.x + i * TPB];
    }
    if (threadIdx.x == 0)
        s_buf[0] = atomicAdd(&g_work[jb], 1u);
    __syncthreads();

    const float4* __restrict__ Wv = reinterpret_cast<const float4*>(W);
    const size_t row_v4 = OUT_DIM / 4;

    long long q0 = 0, q1 = 0, q2 = 0, q3 = 0;       // exact int64 accumulators
    int      p   = 0;
    unsigned cur = s_buf[0];

    while (cur < NCHUNK) {
        // prefetch next chunk id into the OTHER slot (no reader conflict)
        if (threadIdx.x == 0)
            s_buf[p ^ 1] = atomicAdd(&g_work[jb], 1u);

        const int r0 = cur * CROWS;
        float ax = 0.f, ay = 0.f, az = 0.f, aw = 0.f;
        #pragma unroll
        for (int k = 0; k < CROWS; ++k) {
            // streaming load: W never reused — evict-first in L2
            float4 w = __ldcs(Wv + (size_t)(r0 + k) * row_v4 + c4);
            float xv = xs[r0 + k];
            ax = fmaf(xv, w.x, ax);
            ay = fmaf(xv, w.y, ay);
            az = fmaf(xv, w.z, az);
            aw = fmaf(xv, w.w, aw);
        }
        // fixed per-chunk quantization; int64 adds commute exactly ->
        // schedule-independent, bit-deterministic sum.
        q0 += __double2ll_rn((double)ax * FP_SCALE);
        q1 += __double2ll_rn((double)ay * FP_SCALE);
        q2 += __double2ll_rn((double)az * FP_SCALE);
        q3 += __double2ll_rn((double)aw * FP_SCALE);

        __syncthreads();                 // publish s_buf[p^1]; retire cur
        p ^= 1;
        cur = s_buf[p];
    }

    atomicAdd(&g_acc[j0 + 0], (unsigned long long)q0);
    atomicAdd(&g_acc[j0 + 1], (unsigned long long)q1);
    atomicAdd(&g_acc[j0 + 2], (unsigned long long)q2);
    atomicAdd(&g_acc[j0 + 3], (unsigned long long)q3);

    // let the PDL epilogue start launching/prefetching while we drain
    cudaTriggerProgrammaticLaunchCompletion();
}

// Epilogue (PDL secondary): 8192 threads, one output column each.
// Pre-sync: a_hat trace (GEMV-independent). Post-sync: read L2-hot 64KB
// accumulator, convert, LIF; reset accumulator + work queues for replay.
#define EPI_TPB    256
#define EPI_BLOCKS (OUT_DIM / EPI_TPB)     // 32

__global__ void __launch_bounds__(EPI_TPB) lif_epilogue(
    const float* __restrict__ b, const float* __restrict__ u,
    const float* __restrict__ a_hat, const float* __restrict__ x,
    float* __restrict__ out)
{
    const int j = blockIdx.x * EPI_TPB + threadIdx.x;

    // ---- GEMV-independent work before waiting ----
    const float bj = b[j];
    const float uj = u[j];
    out[2 * OUT_DIM + j] = fmaf(SIG_TAU, a_hat[j], x[j]);   // a_hat_new

    // ---- wait for the GEMV grid's memory to be visible ----
    cudaGridDependencySynchronize();

    const long long q = (long long)g_acc[j];
    g_acc[j] = 0ULL;                        // sole reader: reset for replay
    if (j < JBLOCKS) g_work[j] = 0u;        // reset work queues for replay

    const float acc   = (float)((double)q * FP_INVSCALE);
    const float u_pre = fmaf(SIG_TAU, uj, acc + bj);
    const float spike = (u_pre >= V_TH) ? 1.0f : 0.0f;

    out[j]           = spike;
    out[OUT_DIM + j] = u_pre - spike * V_TH;
}

extern "C" void kernel_launch(void* const* d_in, const int* in_sizes, int n_in,
                              void* d_out, int out_size)
{
    const float* W     = (const float*)d_in[0];
    const float* b     = (const float*)d_in[1];
    const float* u     = (const float*)d_in[2];
    const float* a_hat = (const float*)d_in[3];
    const float* x     = (const float*)d_in[4];
    float* out = (float*)d_out;

    gemv_steal<<<NCTAS, TPB>>>(W, x);

    // PDL secondary: may launch while gemv_steal drains.
    cudaLaunchConfig_t cfg = {};
    cfg.gridDim  = dim3(EPI_BLOCKS, 1, 1);
    cfg.blockDim = dim3(EPI_TPB, 1, 1);
    cfg.dynamicSmemBytes = 0;
    cfg.stream = 0;
    cudaLaunchAttribute attr[1];
    attr[0].id = cudaLaunchAttributeProgrammaticStreamSerialization;
    attr[0].val.programmaticStreamSerializationAllowed = 1;
    cfg.attrs = attr;
    cfg.numAttrs = 1;
    cudaLaunchKernelEx(&cfg, lif_epilogue, b, u, a_hat, x, out);
}

// round 15
// speedup vs baseline: 1.6144x; 1.0399x over previous
#include <cuda_runtime.h>

// OTTT step: s, u_new = LIF(sig_tau*u + x@W + b); a_hat_new = sig_tau*a_hat + x
// Inputs (metadata order): W [8192*8192] f32, b [8192], u [8192], a_hat [8192], x [8192]
// Output: flat [s(8192) | u_new(8192) | a_hat_new(8192)] f32
//
// Barrier-free per-WARP work stealing GEMV: 4096 warps pull 8-row chunks from
// 64 queues (one per (j-block, warp-slot)); lane0 atomic + shfl broadcast,
// one-ahead prefetch, zero __syncthreads in the loop -> full MLP, and fast
// SMs absorb slow SMs' work (kills the static-assignment straggler tail).
// Determinism: per-chunk partials quantized to int64 (float-only path:
// __float2ll_rn(p * 2^30)); integer adds commute exactly -> bit-identical
// result under any steal schedule. PDL epilogue converts + LIF + resets.

#define IN_DIM  8192
#define OUT_DIM 8192
#define TPB     256
#define JPT     4                          // columns per thread (float4)
#define JPB     (TPB * JPT)                // 1024 columns per block
#define JBLOCKS (OUT_DIM / JPB)            // 8
#define CTAS_PER_JB 64
#define NCTAS   (JBLOCKS * CTAS_PER_JB)    // 512
#define WPC     (TPB / 32)                 // 8 warp slots per CTA
#define NQUEUE  (JBLOCKS * WPC)            // 64 steal queues
#define CROWS   8                          // rows per chunk
#define NCHUNK  (IN_DIM / CROWS)           // 1024 chunks per queue

// sigmoid(2.0)
#define SIG_TAU 0.8807970779778823f
#define V_TH    1.0f

// fixed-point scale 2^30 (float-exact multiply; added quantization error
// <= 1024 * 2^-31 ~ 5e-7 absolute, invisible at the 1e-3 tolerance)
#define FP_SCALE_F  1073741824.0f          // 2^30
#define FP_INVSCALE (1.0 / 1073741824.0)

__device__ unsigned long long g_acc[OUT_DIM];   // zero at load; epilogue resets
__device__ unsigned int       g_work[NQUEUE];   // zero at load; epilogue resets

__device__ __forceinline__ unsigned warp_pull(unsigned* q, int lane) {
    unsigned v = 0;
    if (lane == 0) v = atomicAdd(q, 1u);
    return __shfl_sync(0xffffffffu, v, 0);
}

__global__ void __launch_bounds__(TPB) gemv_steal(
    const float* __restrict__ W, const float* __restrict__ x)
{
    const int jb   = blockIdx.x & (JBLOCKS - 1);    // 0..7
    const int w    = threadIdx.x >> 5;              // warp slot 0..7
    const int lane = threadIdx.x & 31;
    const int qid  = jb * WPC + w;
    const int j0   = jb * JPB + threadIdx.x * JPT;  // warp covers 512B contiguous
    const int c4   = j0 >> 2;

    __shared__ float xs[IN_DIM];                    // 32 KB: full x vector

    {
        const float4* __restrict__ xv4 = reinterpret_cast<const float4*>(x);
        float4* __restrict__ xs4 = reinterpret_cast<float4*>(xs);
        #pragma unroll
        for (int i = 0; i < IN_DIM / 4 / TPB; ++i)
            xs4[threadIdx.x + i * TPB] = xv4[threadIdx.x + i * TPB];
    }
    __syncthreads();                                // xs ready; no bars after

    const float4* __restrict__ Wv = reinterpret_cast<const float4*>(W);
    const size_t row_v4 = OUT_DIM / 4;

    long long q0 = 0, q1 = 0, q2 = 0, q3 = 0;       // exact int64 accumulators

    unsigned cur = warp_pull(&g_work[qid], lane);
    while (cur < NCHUNK) {
        // prefetch next chunk id; latency hides behind this chunk's loads
        unsigned nxt = warp_pull(&g_work[qid], lane);

        const int r0 = cur * CROWS;
        float ax = 0.f, ay = 0.f, az = 0.f, aw = 0.f;
        #pragma unroll
        for (int k = 0; k < CROWS; ++k) {
            // streaming load: W never reused — evict-first in L2
            float4 wv = __ldcs(Wv + (size_t)(r0 + k) * row_v4 + c4);
            float xv = xs[r0 + k];
            ax = fmaf(xv, wv.x, ax);
            ay = fmaf(xv, wv.y, ay);
            az = fmaf(xv, wv.z, az);
            aw = fmaf(xv, wv.w, aw);
        }
        // fixed per-chunk quantization (power-of-2 scale: float-exact mult);
        // int64 adds commute exactly -> schedule-independent deterministic sum
        q0 += __float2ll_rn(ax * FP_SCALE_F);
        q1 += __float2ll_rn(ay * FP_SCALE_F);
        q2 += __float2ll_rn(az * FP_SCALE_F);
        q3 += __float2ll_rn(aw * FP_SCALE_F);

        cur = nxt;
    }

    atomicAdd(&g_acc[j0 + 0], (unsigned long long)q0);
    atomicAdd(&g_acc[j0 + 1], (unsigned long long)q1);
    atomicAdd(&g_acc[j0 + 2], (unsigned long long)q2);
    atomicAdd(&g_acc[j0 + 3], (unsigned long long)q3);

    // let the PDL epilogue start launching/prefetching while we drain
    cudaTriggerProgrammaticLaunchCompletion();
}

// Epilogue (PDL secondary): 8192 threads, one output column each.
// Pre-sync: a_hat trace (GEMV-independent). Post-sync: read L2-hot 64KB
// accumulator, convert, LIF; reset accumulator + work queues for replay.
#define EPI_TPB    256
#define EPI_BLOCKS (OUT_DIM / EPI_TPB)     // 32

__global__ void __launch_bounds__(EPI_TPB) lif_epilogue(
    const float* __restrict__ b, const float* __restrict__ u,
    const float* __restrict__ a_hat, const float* __restrict__ x,
    float* __restrict__ out)
{
    const int j = blockIdx.x * EPI_TPB + threadIdx.x;

    // ---- GEMV-independent work before waiting ----
    const float bj = b[j];
    const float uj = u[j];
    out[2 * OUT_DIM + j] = fmaf(SIG_TAU, a_hat[j], x[j]);   // a_hat_new

    // ---- wait for the GEMV grid's memory to be visible ----
    cudaGridDependencySynchronize();

    const long long q = (long long)g_acc[j];
    g_acc[j] = 0ULL;                        // sole reader: reset for replay
    if (j < NQUEUE) g_work[j] = 0u;         // reset steal queues for replay

    const float acc   = (float)((double)q * FP_INVSCALE);
    const float u_pre = fmaf(SIG_TAU, uj, acc + bj);
    const float spike = (u_pre >= V_TH) ? 1.0f : 0.0f;

    out[j]           = spike;
    out[OUT_DIM + j] = u_pre - spike * V_TH;
}

extern "C" void kernel_launch(void* const* d_in, const int* in_sizes, int n_in,
                              void* d_out, int out_size)
{
    const float* W     = (const float*)d_in[0];
    const float* b     = (const float*)d_in[1];
    const float* u     = (const float*)d_in[2];
    const float* a_hat = (const float*)d_in[3];
    const float* x     = (const float*)d_in[4];
    float* out = (float*)d_out;

    gemv_steal<<<NCTAS, TPB>>>(W, x);

    // PDL secondary: may launch while gemv_steal drains.
    cudaLaunchConfig_t cfg = {};
    cfg.gridDim  = dim3(EPI_BLOCKS, 1, 1);
    cfg.blockDim = dim3(EPI_TPB, 1, 1);
    cfg.dynamicSmemBytes = 0;
    cfg.stream = 0;
    cudaLaunchAttribute attr[1];
    attr[0].id = cudaLaunchAttributeProgrammaticStreamSerialization;
    attr[0].val.programmaticStreamSerializationAllowed = 1;
    cfg.attrs = attr;
    cfg.numAttrs = 1;
    cudaLaunchKernelEx(&cfg, lif_epilogue, b, u, a_hat, x, out);
}

// round 16
// speedup vs baseline: 1.9495x; 1.2076x over previous
#include <cuda_runtime.h>

// OTTT step: s, u_new = LIF(sig_tau*u + x@W + b); a_hat_new = sig_tau*a_hat + x
// Inputs (metadata order): W [8192*8192] f32, b [8192], u [8192], a_hat [8192], x [8192]
// Output: flat [s(8192) | u_new(8192) | a_hat_new(8192)] f32
//
// Fine-grained split-K GEMV: 2048 CTAs (8 j-blocks x 256 splits of 32 rows).
// Grid >> residency, so the HARDWARE CTA scheduler load-balances across slow/
// fast SMs (software stealing failed: dynamic addressing killed MLP; static
// fine CTAs keep compile-time addresses + front-batched loads). Reduction via
// int64 fixed-point atomics: float-exact *2^30 quantize, integer adds commute
// exactly -> bit-deterministic for any CTA schedule. PDL epilogue converts,
// applies LIF, and resets the accumulator for graph replay.

#define IN_DIM  8192
#define OUT_DIM 8192
#define SPLITS  256
#define ROWS_PER_SPLIT (IN_DIM / SPLITS)   // 32
#define TPB     256
#define JPT     4                          // columns per thread (float4)
#define JPB     (TPB * JPT)                // 1024 columns per block
#define JBLOCKS (OUT_DIM / JPB)            // 8

// sigmoid(2.0)
#define SIG_TAU 0.8807970779778823f
#define V_TH    1.0f

// fixed-point scale 2^30 (power-of-2: float multiply exact; per-split
// quantization error <= 256 * 2^-31 ~ 1.2e-7 absolute -> invisible at 1e-3)
#define FP_SCALE_F  1073741824.0f          // 2^30
#define FP_INVSCALE (1.0 / 1073741824.0)

__device__ unsigned long long g_acc[OUT_DIM];   // zero at load; epilogue resets

__global__ void __launch_bounds__(TPB) gemv_partial(
    const float* __restrict__ W, const float* __restrict__ x)
{
    const int jb    = blockIdx.x;           // 0..7
    const int split = blockIdx.y;           // 0..255
    const int j0    = jb * JPB + threadIdx.x * JPT;
    const int i0    = split * ROWS_PER_SPLIT;

    __shared__ float xs[ROWS_PER_SPLIT];
    if (threadIdx.x < ROWS_PER_SPLIT)
        xs[threadIdx.x] = x[i0 + threadIdx.x];
    __syncthreads();

    const float4* __restrict__ Wv =
        reinterpret_cast<const float4*>(W + (size_t)i0 * OUT_DIM + j0);
    const size_t row_v4 = OUT_DIM / 4;

    float ax = 0.f, ay = 0.f, az = 0.f, aw = 0.f;

    #pragma unroll 8
    for (int r = 0; r < ROWS_PER_SPLIT; ++r) {
        // streaming load: W is 268MB, never reused — evict-first in L2
        float4 w = __ldcs(Wv + (size_t)r * row_v4);
        float xv = xs[r];
        ax = fmaf(xv, w.x, ax);
        ay = fmaf(xv, w.y, ay);
        az = fmaf(xv, w.z, az);
        aw = fmaf(xv, w.w, aw);
    }

    // deterministic reduction: fixed per-split quantization (split -> fixed
    // rows, regardless of which SM ran it); int64 adds commute exactly.
    long long q0 = __float2ll_rn(ax * FP_SCALE_F);
    long long q1 = __float2ll_rn(ay * FP_SCALE_F);
    long long q2 = __float2ll_rn(az * FP_SCALE_F);
    long long q3 = __float2ll_rn(aw * FP_SCALE_F);
    atomicAdd(&g_acc[j0 + 0], (unsigned long long)q0);
    atomicAdd(&g_acc[j0 + 1], (unsigned long long)q1);
    atomicAdd(&g_acc[j0 + 2], (unsigned long long)q2);
    atomicAdd(&g_acc[j0 + 3], (unsigned long long)q3);

    // let the PDL epilogue start launching/prefetching while we drain
    cudaTriggerProgrammaticLaunchCompletion();
}

// Epilogue (PDL secondary): 8192 threads, one output column each.
// Pre-sync: a_hat trace (GEMV-independent). Post-sync: read L2-hot 64KB
// accumulator, convert, LIF; reset accumulator for the next graph replay.
#define EPI_TPB    256
#define EPI_BLOCKS (OUT_DIM / EPI_TPB)     // 32

__global__ void __launch_bounds__(EPI_TPB) lif_epilogue(
    const float* __restrict__ b, const float* __restrict__ u,
    const float* __restrict__ a_hat, const float* __restrict__ x,
    float* __restrict__ out)
{
    const int j = blockIdx.x * EPI_TPB + threadIdx.x;

    // ---- GEMV-independent work before waiting ----
    const float bj = b[j];
    const float uj = u[j];
    out[2 * OUT_DIM + j] = fmaf(SIG_TAU, a_hat[j], x[j]);   // a_hat_new

    // ---- wait for the GEMV grid's memory to be visible ----
    cudaGridDependencySynchronize();

    const long long q = (long long)g_acc[j];
    g_acc[j] = 0ULL;                        // sole reader: reset for replay

    const float acc   = (float)((double)q * FP_INVSCALE);
    const float u_pre = fmaf(SIG_TAU, uj, acc + bj);
    const float spike = (u_pre >= V_TH) ? 1.0f : 0.0f;

    out[j]           = spike;
    out[OUT_DIM + j] = u_pre - spike * V_TH;
}

extern "C" void kernel_launch(void* const* d_in, const int* in_sizes, int n_in,
                              void* d_out, int out_size)
{
    const float* W     = (const float*)d_in[0];
    const float* b     = (const float*)d_in[1];
    const float* u     = (const float*)d_in[2];
    const float* a_hat = (const float*)d_in[3];
    const float* x     = (const float*)d_in[4];
    float* out = (float*)d_out;

    dim3 grid(JBLOCKS, SPLITS);
    gemv_partial<<<grid, TPB>>>(W, x);

    // PDL secondary: may launch while gemv_partial drains.
    cudaLaunchConfig_t cfg = {};
    cfg.gridDim  = dim3(EPI_BLOCKS, 1, 1);
    cfg.blockDim = dim3(EPI_TPB, 1, 1);
    cfg.dynamicSmemBytes = 0;
    cfg.stream = 0;
    cudaLaunchAttribute attr[1];
    attr[0].id = cudaLaunchAttributeProgrammaticStreamSerialization;
    attr[0].val.programmaticStreamSerializationAllowed = 1;
    cfg.attrs = attr;
    cfg.numAttrs = 1;
    cudaLaunchKernelEx(&cfg, lif_epilogue, b, u, a_hat, x, out);
}

// round 17
// speedup vs baseline: 2.1184x; 1.0866x over previous
#include <cuda_runtime.h>

// OTTT step: s, u_new = LIF(sig_tau*u + x@W + b); a_hat_new = sig_tau*a_hat + x
// Inputs (metadata order): W [8192*8192] f32, b [8192], u [8192], a_hat [8192], x [8192]
// Output: flat [s(8192) | u_new(8192) | a_hat_new(8192)] f32
//
// Split-K GEMV at SPLITS=128: 1024 CTAs of 64 rows = ~1.7 waves. Wave-2 CTAs
// are placed by the hardware scheduler's work-steal path, so slow SMs get
// fewer CTAs and the straggler tail quantum halves vs the 512-CTA single
// wave, while 64 front-batched LDG.128 per thread keeps full MLP (the
// failure of 32-row CTAs in R16). Reduction via int64 fixed-point atomics:
// float-exact *2^30 quantize; integer adds commute exactly -> result is
// bit-deterministic under any CTA schedule. PDL epilogue converts + LIF +
// resets the accumulator for graph replay.

#define IN_DIM  8192
#define OUT_DIM 8192
#define SPLITS  128
#define ROWS_PER_SPLIT (IN_DIM / SPLITS)   // 64
#define TPB     256
#define JPT     4                          // columns per thread (float4)
#define JPB     (TPB * JPT)                // 1024 columns per block
#define JBLOCKS (OUT_DIM / JPB)            // 8

// sigmoid(2.0)
#define SIG_TAU 0.8807970779778823f
#define V_TH    1.0f

// fixed-point scale 2^30 (power-of-2: float multiply exact; per-split
// quantization error <= 128 * 2^-31 ~ 6e-8 absolute -> invisible at 1e-3)
#define FP_SCALE_F  1073741824.0f          // 2^30
#define FP_INVSCALE (1.0 / 1073741824.0)

__device__ unsigned long long g_acc[OUT_DIM];   // zero at load; epilogue resets

__global__ void __launch_bounds__(TPB) gemv_partial(
    const float* __restrict__ W, const float* __restrict__ x)
{
    const int jb    = blockIdx.x;           // 0..7
    const int split = blockIdx.y;           // 0..127
    const int j0    = jb * JPB + threadIdx.x * JPT;
    const int i0    = split * ROWS_PER_SPLIT;

    __shared__ float xs[ROWS_PER_SPLIT];
    if (threadIdx.x < ROWS_PER_SPLIT)
        xs[threadIdx.x] = x[i0 + threadIdx.x];
    __syncthreads();

    const float4* __restrict__ Wv =
        reinterpret_cast<const float4*>(W + (size_t)i0 * OUT_DIM + j0);
    const size_t row_v4 = OUT_DIM / 4;

    float ax = 0.f, ay = 0.f, az = 0.f, aw = 0.f;

    #pragma unroll 8
    for (int r = 0; r < ROWS_PER_SPLIT; ++r) {
        // streaming load: W is 268MB, never reused — evict-first in L2
        float4 w = __ldcs(Wv + (size_t)r * row_v4);
        float xv = xs[r];
        ax = fmaf(xv, w.x, ax);
        ay = fmaf(xv, w.y, ay);
        az = fmaf(xv, w.z, az);
        aw = fmaf(xv, w.w, aw);
    }

    // deterministic reduction: fixed per-split quantization (split -> fixed
    // rows, regardless of which SM/wave ran it); int64 adds commute exactly.
    long long q0 = __float2ll_rn(ax * FP_SCALE_F);
    long long q1 = __float2ll_rn(ay * FP_SCALE_F);
    long long q2 = __float2ll_rn(az * FP_SCALE_F);
    long long q3 = __float2ll_rn(aw * FP_SCALE_F);
    atomicAdd(&g_acc[j0 + 0], (unsigned long long)q0);
    atomicAdd(&g_acc[j0 + 1], (unsigned long long)q1);
    atomicAdd(&g_acc[j0 + 2], (unsigned long long)q2);
    atomicAdd(&g_acc[j0 + 3], (unsigned long long)q3);

    // let the PDL epilogue start launching/prefetching while we drain
    cudaTriggerProgrammaticLaunchCompletion();
}

// Epilogue (PDL secondary): 8192 threads, one output column each.
// Pre-sync: a_hat trace (GEMV-independent). Post-sync: read L2-hot 64KB
// accumulator, convert, LIF; reset accumulator for the next graph replay.
#define EPI_TPB    256
#define EPI_BLOCKS (OUT_DIM / EPI_TPB)     // 32

__global__ void __launch_bounds__(EPI_TPB) lif_epilogue(
    const float* __restrict__ b, const float* __restrict__ u,
    const float* __restrict__ a_hat, const float* __restrict__ x,
    float* __restrict__ out)
{
    const int j = blockIdx.x * EPI_TPB + threadIdx.x;

    // ---- GEMV-independent work before waiting ----
    const float bj = b[j];
    const float uj = u[j];
    out[2 * OUT_DIM + j] = fmaf(SIG_TAU, a_hat[j], x[j]);   // a_hat_new

    // ---- wait for the GEMV grid's memory to be visible ----
    cudaGridDependencySynchronize();

    const long long q = (long long)g_acc[j];
    g_acc[j] = 0ULL;                        // sole reader: reset for replay

    const float acc   = (float)((double)q * FP_INVSCALE);
    const float u_pre = fmaf(SIG_TAU, uj, acc + bj);
    const float spike = (u_pre >= V_TH) ? 1.0f : 0.0f;

    out[j]           = spike;
    out[OUT_DIM + j] = u_pre - spike * V_TH;
}

extern "C" void kernel_launch(void* const* d_in, const int* in_sizes, int n_in,
                              void* d_out, int out_size)
{
    const float* W     = (const float*)d_in[0];
    const float* b     = (const float*)d_in[1];
    const float* u     = (const float*)d_in[2];
    const float* a_hat = (const float*)d_in[3];
    const float* x     = (const float*)d_in[4];
    float* out = (float*)d_out;

    dim3 grid(JBLOCKS, SPLITS);
    gemv_partial<<<grid, TPB>>>(W, x);

    // PDL secondary: may launch while gemv_partial drains.
    cudaLaunchConfig_t cfg = {};
    cfg.gridDim  = dim3(EPI_BLOCKS, 1, 1);
    cfg.blockDim = dim3(EPI_TPB, 1, 1);
    cfg.dynamicSmemBytes = 0;
    cfg.stream = 0;
    cudaLaunchAttribute attr[1];
    attr[0].id = cudaLaunchAttributeProgrammaticStreamSerialization;
    attr[0].val.programmaticStreamSerializationAllowed = 1;
    cfg.attrs = attr;
    cfg.numAttrs = 1;
    cudaLaunchKernelEx(&cfg, lif_epilogue, b, u, a_hat, x, out);
}